// round 2
// baseline (speedup 1.0000x reference)
#include <cuda_runtime.h>

#define NN 200000
#define EE 6400000
#define GG 2048
#define HH 32

// ---------------- scratch (device globals; no allocations allowed) ----------
__device__ float g_agg1[NN];
__device__ float g_deg[NN];
__device__ __align__(16) float g_h1[NN * HH];   // layer1 output (pre/post BN in place)
__device__ __align__(16) float g_h2[NN * HH];   // layer2 agg -> pre-BN -> post-BN (in place)
__device__ float g_score[NN];
__device__ float g_stats[4 * HH];               // [sum1 | sumsq1 | sum2 | sumsq2]
__device__ float g_scale1[HH], g_shift1[HH], g_scale2[HH], g_shift2[HH];
__device__ unsigned int g_smax[GG];             // order-preserving encoded float max
__device__ float g_denom[GG];
__device__ float g_numer[GG * HH];

// ---------------- kernels ---------------------------------------------------

__global__ void k_zero() {
    int i = blockIdx.x * blockDim.x + threadIdx.x;   // grid covers NN*HH exactly
    g_h2[i] = 0.f;
    if (i < NN) { g_agg1[i] = 0.f; g_deg[i] = 0.f; }
    if (i < GG) { g_denom[i] = 0.f; g_smax[i] = 0u; }
    if (i < GG * HH) g_numer[i] = 0.f;
    if (i < 4 * HH) g_stats[i] = 0.f;
}

// edge pass 1: scalar mean-agg of x
__global__ void k_edge1(const int* __restrict__ ei, const float* __restrict__ x) {
    int e = blockIdx.x * blockDim.x + threadIdx.x;   // grid covers EE exactly
    int s = __ldg(&ei[e]);
    int d = __ldg(&ei[EE + e]);
    atomicAdd(&g_agg1[d], __ldg(&x[s]));
    atomicAdd(&g_deg[d], 1.0f);
}

// layer1 node update: h1pre = aggmean*W1l + b1l + x*W1r ; accumulate BN1 stats
__global__ void k_l1(const float* __restrict__ x, const float* __restrict__ W1l,
                     const float* __restrict__ b1l, const float* __restrict__ W1r) {
    int lane = threadIdx.x & 31;
    int warp = (blockIdx.x * blockDim.x + threadIdx.x) >> 5;
    int nwarps = (gridDim.x * blockDim.x) >> 5;
    float wl = __ldg(&W1l[lane]), wr = __ldg(&W1r[lane]), bb = __ldg(&b1l[lane]);
    float s = 0.f, s2 = 0.f;
    for (int n = warp; n < NN; n += nwarps) {
        float am = g_agg1[n] / fmaxf(g_deg[n], 1.0f);
        float xv = __ldg(&x[n]);
        float v = am * wl + bb + xv * wr;
        g_h1[n * HH + lane] = v;
        s += v; s2 += v * v;
    }
    atomicAdd(&g_stats[lane], s);
    atomicAdd(&g_stats[HH + lane], s2);
}

// finalize BN stats -> scale/shift
__global__ void k_bnfin(const float* __restrict__ gamma, const float* __restrict__ beta,
                        int which) {
    int f = threadIdx.x;
    int off = which ? 2 * HH : 0;
    float inv_n = 1.0f / (float)NN;
    float mean = g_stats[off + f] * inv_n;
    float var  = g_stats[off + HH + f] * inv_n - mean * mean;
    float sc = __ldg(&gamma[f]) * rsqrtf(var + 1e-5f);
    float sh = __ldg(&beta[f]) - mean * sc;
    if (which) { g_scale2[f] = sc; g_shift2[f] = sh; }
    else       { g_scale1[f] = sc; g_shift1[f] = sh; }
}

// apply BN1 + relu in place on h1
__global__ void k_bn1() {
    int i = blockIdx.x * blockDim.x + threadIdx.x;   // grid covers NN*HH exactly
    int f = i & (HH - 1);
    float v = g_h1[i] * g_scale1[f] + g_shift1[f];
    g_h1[i] = fmaxf(v, 0.f);
}

// edge pass 2: gather h1[src] (32 floats) and vector-reduce into g_h2[dst]
__global__ void k_edge2(const int* __restrict__ ei) {
    long long t = (long long)blockIdx.x * blockDim.x + threadIdx.x;  // covers EE*8 exactly
    int e = (int)(t >> 3);
    int k = (int)(t & 7);
    int s = __ldg(&ei[e]);
    int d = __ldg(&ei[EE + e]);
    float4 v = __ldg((const float4*)&g_h1[s * HH + k * 4]);
    float* p = &g_h2[d * HH + k * 4];
    asm volatile("red.global.add.v4.f32 [%0], {%1,%2,%3,%4};"
                 :: "l"(p), "f"(v.x), "f"(v.y), "f"(v.z), "f"(v.w)
                 : "memory");
}

// layer2 node update: h2pre = aggmean@W2l^T + b2l + h1@W2r^T (in place in g_h2); BN2 stats
__global__ void k_l2(const float* __restrict__ W2l, const float* __restrict__ b2l,
                     const float* __restrict__ W2r) {
    __shared__ float sWl[HH * HH], sWr[HH * HH], sb[HH];
    for (int t = threadIdx.x; t < HH * HH; t += blockDim.x) {
        int i = t / HH, j = t % HH;                 // store transposed: [j][i]
        sWl[j * HH + i] = __ldg(&W2l[t]);
        sWr[j * HH + i] = __ldg(&W2r[t]);
    }
    if (threadIdx.x < HH) sb[threadIdx.x] = __ldg(&b2l[threadIdx.x]);
    __syncthreads();

    int lane = threadIdx.x & 31;
    int warp = (blockIdx.x * blockDim.x + threadIdx.x) >> 5;
    int nwarps = (gridDim.x * blockDim.x) >> 5;
    float s = 0.f, s2 = 0.f;
    for (int n = warp; n < NN; n += nwarps) {
        float dc = fmaxf(g_deg[n], 1.0f);
        float av = g_h2[n * HH + lane] / dc;
        float hv = g_h1[n * HH + lane];
        float acc = sb[lane];
#pragma unroll
        for (int j = 0; j < HH; j++) {
            float aj = __shfl_sync(0xffffffffu, av, j);
            float hj = __shfl_sync(0xffffffffu, hv, j);
            acc += aj * sWl[j * HH + lane] + hj * sWr[j * HH + lane];
        }
        g_h2[n * HH + lane] = acc;
        s += acc; s2 += acc * acc;
    }
    atomicAdd(&g_stats[2 * HH + lane], s);
    atomicAdd(&g_stats[3 * HH + lane], s2);
}

// BN2+relu in place, gate score + segment max (encoded unsigned atomicMax)
__global__ void k_score(const int* __restrict__ batch,
                        const float* __restrict__ gw, const float* __restrict__ gb) {
    int lane = threadIdx.x & 31;
    int warp = (blockIdx.x * blockDim.x + threadIdx.x) >> 5;
    int nwarps = (gridDim.x * blockDim.x) >> 5;
    float w = __ldg(&gw[lane]);
    float sc2 = g_scale2[lane], sh2 = g_shift2[lane];
    float gbias = __ldg(&gb[0]);
    for (int n = warp; n < NN; n += nwarps) {
        float v = fmaxf(g_h2[n * HH + lane] * sc2 + sh2, 0.f);
        g_h2[n * HH + lane] = v;
        float sc = v * w;
#pragma unroll
        for (int o = 16; o; o >>= 1) sc += __shfl_xor_sync(0xffffffffu, sc, o);
        if (lane == 0) {
            sc += gbias;
            g_score[n] = sc;
            unsigned b = (unsigned)__ldg(&batch[n]);
            unsigned bits = __float_as_uint(sc);
            unsigned enc = (bits & 0x80000000u) ? ~bits : (bits | 0x80000000u);
            atomicMax(&g_smax[b], enc);
        }
    }
}

// segment softmax numerator/denominator accumulation
__global__ void k_soft(const int* __restrict__ batch) {
    int lane = threadIdx.x & 31;
    int warp = (blockIdx.x * blockDim.x + threadIdx.x) >> 5;
    int nwarps = (gridDim.x * blockDim.x) >> 5;
    for (int n = warp; n < NN; n += nwarps) {
        int b = __ldg(&batch[n]);
        unsigned enc = g_smax[b];
        unsigned bits = (enc & 0x80000000u) ? (enc & 0x7fffffffu) : ~enc;
        float sm = __uint_as_float(bits);
        float ex = expf(g_score[n] - sm);
        atomicAdd(&g_numer[b * HH + lane], ex * g_h2[n * HH + lane]);
        if (lane == 0) atomicAdd(&g_denom[b], ex);
    }
}

// final: out[g] = sigmoid( (numer/denom) . lin_w + lin_b )
__global__ void k_out(const float* __restrict__ lw, const float* __restrict__ lb,
                      float* __restrict__ out) {
    int lane = threadIdx.x & 31;
    int g = (blockIdx.x * blockDim.x + threadIdx.x) >> 5;
    if (g >= GG) return;
    float v = g_numer[g * HH + lane] / g_denom[g] * __ldg(&lw[lane]);
#pragma unroll
    for (int o = 16; o; o >>= 1) v += __shfl_xor_sync(0xffffffffu, v, o);
    if (lane == 0) out[g] = 1.0f / (1.0f + expf(-v));
}

// ---------------- launch ----------------------------------------------------

extern "C" void kernel_launch(void* const* d_in, const int* in_sizes, int n_in,
                              void* d_out, int out_size) {
    const float* x     = (const float*)d_in[0];
    const int*   ei    = (const int*)d_in[1];
    const int*   batch = (const int*)d_in[2];
    const float* W1l   = (const float*)d_in[3];
    const float* b1l   = (const float*)d_in[4];
    const float* W1r   = (const float*)d_in[5];
    const float* W2l   = (const float*)d_in[6];
    const float* b2l   = (const float*)d_in[7];
    const float* W2r   = (const float*)d_in[8];
    const float* g1    = (const float*)d_in[9];
    const float* be1   = (const float*)d_in[10];
    const float* g2    = (const float*)d_in[11];
    const float* be2   = (const float*)d_in[12];
    const float* gate_w= (const float*)d_in[13];
    const float* gate_b= (const float*)d_in[14];
    const float* lin_w = (const float*)d_in[15];
    const float* lin_b = (const float*)d_in[16];
    float* out = (float*)d_out;

    const int T = 256;
    const int blocksNH = (NN * HH) / T;          // 25000, covers NN*HH exactly
    const int blocksE  = EE / T;                 // 25000
    const int blocksE8 = (EE * 8) / T;           // 200000
    const int blocksW  = 2048;                   // grid-stride warp kernels

    k_zero<<<blocksNH, T>>>();
    k_edge1<<<blocksE, T>>>(ei, x);
    k_l1<<<blocksW, T>>>(x, W1l, b1l, W1r);
    k_bnfin<<<1, HH>>>(g1, be1, 0);
    k_bn1<<<blocksNH, T>>>();
    k_edge2<<<blocksE8, T>>>(ei);
    k_l2<<<blocksW, T>>>(W2l, b2l, W2r);
    k_bnfin<<<1, HH>>>(g2, be2, 1);
    k_score<<<blocksW, T>>>(batch, gate_w, gate_b);
    k_soft<<<blocksW, T>>>(batch);
    k_out<<<(GG * 32 + T - 1) / T, T>>>(lin_w, lin_b, out);
}